// round 7
// baseline (speedup 1.0000x reference)
#undef NDEBUG
#include <cuda_runtime.h>
#include <cuda_bf16.h>
#include <cstdio>
#include <cassert>

// ---------------- problem constants ----------------
#define N_NODES  50000
#define N_EDGES  800000
#define N_REL    3
#define N_GRAPHS 500
#define EMB      128
#define IN_DIM   384      // 3*EMB
#define HID      256
#define NCOL     1024     // 3*HID + HID (relation blocks + root block)
#define N_CLASS  10

// ---------------- scratch (device globals; no cudaMalloc allowed) ----------------
// NOTE: these are ONLY referenced from device code. Passing a __device__ array
// from host code passes the host shadow symbol's address; on GB300 (ATS) the
// kernel then silently reads/writes HOST memory — that was the Round 1-5 bug.
__device__ __align__(16) float d_h0[(size_t)N_NODES * IN_DIM];        // 76.8 MB
__device__ __align__(16) float d_G[(size_t)N_NODES * NCOL];           // 204.8 MB
__device__ __align__(16) float d_acc[(size_t)N_NODES * HID];          // 51.2 MB
__device__ __align__(16) float d_Wcat1[IN_DIM * NCOL];                // 384x1024
__device__ __align__(16) float d_Wcat2[HID * NCOL];                   // 256x1024
__device__ int   d_cnt3[N_NODES * N_REL];
__device__ float d_invcnt[N_NODES * N_REL];
__device__ int   d_offs[N_NODES + 1];
__device__ int   d_fill[N_NODES];
__device__ int   d_elist[N_EDGES];                      // src | (etype<<20), sorted by dst
__device__ float d_ew[N_EDGES];                         // 1/cnt weight per sorted edge
__device__ int   d_gcnt[N_GRAPHS];
__device__ float d_invg[N_GRAPHS];
__device__ float d_pooled[N_GRAPHS * HID];

// resolved input pointers (device-side role assignment)
__device__ const int*   RP_s;
__device__ const int*   RP_c;
__device__ const int*   RP_p;
__device__ const int*   RP_batch;
__device__ const float* RP_semb;
__device__ const float* RP_cemb;
__device__ int d_maxv[4];
__device__ int d_role_ok;

// ---------------- diagnostics (parallel, cheap) ----------------
struct SizesParam { int n; int v[24]; };

__global__ void chk_mapping_fail(SizesParam sp, int code) {
    printf("MAPPING FAIL code=%d n_in=%d\n", code, sp.n);
    for (int i = 0; i < sp.n && i < 24; i++) printf("  in_sizes[%d]=%d\n", i, sp.v[i]);
    assert(0 && "input size mapping failed");
}

__global__ void chk_roles() {
    if (d_role_ok != 1)
        printf("ROLE FAIL maxv = %d %d %d %d\n", d_maxv[0], d_maxv[1], d_maxv[2], d_maxv[3]);
    assert(d_role_ok == 1);
}

__device__ float block_abssum(const float* p, int n) {
    __shared__ float red[256];
    float s = 0.f;
    for (int k = threadIdx.x; k < n; k += 256) s += fabsf(p[k]);
    red[threadIdx.x] = s;
    __syncthreads();
    for (int off = 128; off; off >>= 1) {
        if (threadIdx.x < (unsigned)off) red[threadIdx.x] += red[threadIdx.x + off];
        __syncthreads();
    }
    return red[0];
}

__global__ void chk_h0() {
    float s = block_abssum(d_h0, IN_DIM);
    if (threadIdx.x == 0) {
        if (!(isfinite(s) && s > 0.f && s < 1e7f)) printf("H0 FAIL rowsum=%f\n", s);
        assert(isfinite(s) && s > 0.f && s < 1e7f);
    }
}

__global__ void chk_w() {
    float s1 = block_abssum(d_Wcat1, NCOL);
    float s2 = block_abssum(d_Wcat2, NCOL);
    if (threadIdx.x == 0) {
        if (!(isfinite(s1) && s1 > 0.f && isfinite(s2) && s2 > 0.f))
            printf("W FAIL s1=%f s2=%f\n", s1, s2);
        assert(isfinite(s1) && s1 > 0.f);
        assert(isfinite(s2) && s2 > 0.f);
    }
}

__global__ void chk_offs() {
    if (threadIdx.x == 0) {
        if (d_offs[N_NODES] != N_EDGES)
            printf("OFFS FAIL total=%d (want %d)\n", d_offs[N_NODES], N_EDGES);
        assert(d_offs[N_NODES] == N_EDGES);
    }
}

__global__ void chk_G() {
    float s = block_abssum(d_G, NCOL);
    if (threadIdx.x == 0) {
        if (!(isfinite(s) && s > 0.f)) printf("G FAIL rowsum=%f\n", s);
        assert(isfinite(s) && s > 0.f);
    }
}

__global__ void chk_acc() {
    float s = block_abssum(d_acc, HID);
    if (threadIdx.x == 0) {
        if (!isfinite(s)) printf("ACC FAIL rowsum=%f\n", s);
        assert(isfinite(s));
    }
}

// ---------------- input resolver ----------------
__global__ void classify_ints(const int* a0, const int* a1, const int* a2, const int* a3) {
    const int* arr[4] = {a0, a1, a2, a3};
    const int* a = arr[blockIdx.y];
    int i = blockIdx.x * blockDim.x + threadIdx.x;
    int stride = gridDim.x * blockDim.x;
    int m = 0;
    for (int k = i; k < N_NODES; k += stride) m = max(m, a[k]);
#pragma unroll
    for (int off = 16; off; off >>= 1) m = max(m, __shfl_xor_sync(0xffffffffu, m, off));
    if ((threadIdx.x & 31) == 0) atomicMax(&d_maxv[blockIdx.y], m);
}

__global__ void assign_roles(const int* a0, const int* a1, const int* a2, const int* a3,
                             const float* t0, const float* t1) {
    const int* arr[4] = {a0, a1, a2, a3};
    int small[2]; int ns = 0; int ip = -1, ib = -1;
    for (int k = 0; k < 4; k++) {
        int m = d_maxv[k];
        if (m <= 7)        { if (ns < 2) small[ns] = k; ns++; }
        else if (m <= 127) ip = k;
        else               ib = k;
    }
    if (ns == 2 && ip >= 0 && ib >= 0) {
        RP_s = arr[small[0]]; RP_c = arr[small[1]];
        RP_p = arr[ip];       RP_batch = arr[ib];
        d_role_ok = 1;
    } else {  // fallback: signature order (still flag for diagnosis)
        RP_s = a0; RP_c = a1; RP_p = a2; RP_batch = a3;
        d_role_ok = 0;
    }
    RP_semb = t0; RP_cemb = t1;
}

// ---------------- utility kernels ----------------
__global__ void zero_misc() {
    int i = blockIdx.x * blockDim.x + threadIdx.x;
    int stride = gridDim.x * blockDim.x;
    for (int k = i; k < N_NODES * N_REL; k += stride) d_cnt3[k] = 0;
    for (int k = i; k < N_NODES;         k += stride) d_fill[k] = 0;
    for (int k = i; k < N_GRAPHS;        k += stride) d_gcnt[k] = 0;
    for (int k = i; k < N_GRAPHS * HID;  k += stride) d_pooled[k] = 0.f;
    if (i < 4) d_maxv[i] = 0;
    if (i == 4) d_role_ok = -1;
}

// Build Wcat = [W_r0 | W_r1 | W_r2 | root] as (K x 1024) row-major
__global__ void repack_w(const float* __restrict__ W1, const float* __restrict__ root1,
                         const float* __restrict__ W2, const float* __restrict__ root2) {
    int i = blockIdx.x * blockDim.x + threadIdx.x;
    if (i < IN_DIM * NCOL) {
        int k = i >> 10, col = i & 1023;
        float v;
        if (col < N_REL * HID) {
            int r = col >> 8, j = col & 255;
            v = W1[((size_t)r * IN_DIM + k) * HID + j];
        } else {
            v = root1[k * HID + (col - N_REL * HID)];
        }
        d_Wcat1[i] = v;
    }
    if (i < HID * NCOL) {
        int k = i >> 10, col = i & 1023;
        float v;
        if (col < N_REL * HID) {
            int r = col >> 8, j = col & 255;
            v = W2[((size_t)r * HID + k) * HID + j];
        } else {
            v = root2[k * HID + (col - N_REL * HID)];
        }
        d_Wcat2[i] = v;
    }
}

// h0[n] = [shape_emb[s[n]] | color_emb[c[n]] | pos_emb[p[n]]]; also graph node counts
__global__ void gather_h0(const float* __restrict__ pe) {
    int i = blockIdx.x * blockDim.x + threadIdx.x;
    if (i >= N_NODES * 96) return;          // 96 float4 chunks per node
    int n = i / 96, q = i % 96;
    int seg = q >> 5;                        // which embedding table
    int off = (q & 31) << 2;                 // float offset within 128
    const float* row;
    if (seg == 0)      row = RP_semb + (size_t)min(max(RP_s[n], 0), 7) * EMB;
    else if (seg == 1) row = RP_cemb + (size_t)min(max(RP_c[n], 0), 7) * EMB;
    else               row = pe      + (size_t)min(max(RP_p[n], 0), 127) * EMB;
    *(float4*)(d_h0 + (size_t)n * IN_DIM + seg * EMB + off) = *(const float4*)(row + off);
    if (q == 0) atomicAdd(&d_gcnt[min(max(RP_batch[n], 0), N_GRAPHS - 1)], 1);
}

__global__ void count_edges(const int* __restrict__ dst, const int* __restrict__ et) {
    int i = blockIdx.x * blockDim.x + threadIdx.x;
    if (i < N_EDGES) {
        int d = min(max(dst[i], 0), N_NODES - 1);
        int t = min(max(et[i], 0), N_REL - 1);
        atomicAdd(&d_cnt3[d * N_REL + t], 1);
    }
}

__global__ void inv_counts() {
    int i = blockIdx.x * blockDim.x + threadIdx.x;
    int stride = gridDim.x * blockDim.x;
    for (int k = i; k < N_NODES * N_REL; k += stride)
        d_invcnt[k] = 1.0f / fmaxf((float)d_cnt3[k], 1.0f);
    for (int k = i; k < N_GRAPHS; k += stride)
        d_invg[k] = 1.0f / fmaxf((float)d_gcnt[k], 1.0f);
}

// exclusive scan of per-dst edge counts (single block, sequential tiles)
__global__ void scan_offsets() {
    __shared__ int tile[1024];
    __shared__ int carry_s;
    if (threadIdx.x == 0) carry_s = 0;
    __syncthreads();
    for (int base = 0; base < N_NODES; base += 1024) {
        int n = base + (int)threadIdx.x;
        int v = 0;
        if (n < N_NODES)
            v = d_cnt3[3 * n] + d_cnt3[3 * n + 1] + d_cnt3[3 * n + 2];
        tile[threadIdx.x] = v;
        __syncthreads();
        for (int off = 1; off < 1024; off <<= 1) {
            int t = (threadIdx.x >= (unsigned)off) ? tile[threadIdx.x - off] : 0;
            __syncthreads();
            tile[threadIdx.x] += t;
            __syncthreads();
        }
        if (n < N_NODES) d_offs[n] = carry_s + tile[threadIdx.x] - v;   // exclusive
        __syncthreads();
        if (threadIdx.x == 0) carry_s += tile[1023];
        __syncthreads();
    }
    if (threadIdx.x == 0) d_offs[N_NODES] = carry_s;
}

// counting-sort edges into per-dst contiguous lists, with per-edge 1/cnt weight
__global__ void scatter_edges(const int* __restrict__ src, const int* __restrict__ dst,
                              const int* __restrict__ et) {
    int i = blockIdx.x * blockDim.x + threadIdx.x;
    if (i >= N_EDGES) return;
    int d = min(max(dst[i], 0), N_NODES - 1);
    int t = min(max(et[i], 0), N_REL - 1);
    int sv = min(max(src[i], 0), N_NODES - 1);
    int pos = d_offs[d] + atomicAdd(&d_fill[d], 1);
    if (pos >= 0 && pos < N_EDGES) {
        d_elist[pos] = sv | (t << 20);
        d_ew[pos]    = d_invcnt[d * N_REL + t];
    }
}

// ---------------- SGEMM: d_G(M x 1024) = A(M x K) * B(K x 1024) ----------------
// A/B/C are bound INSIDE device code (never pass __device__ globals from host!)
template<int K, bool LAYER2>
__global__ __launch_bounds__(256)
void sgemm_k(int M) {
    const float* __restrict__ A = LAYER2 ? d_acc   : d_h0;
    const float* __restrict__ B = LAYER2 ? d_Wcat2 : d_Wcat1;
    float* __restrict__ C = d_G;

    __shared__ __align__(16) float As[16][132];   // [k][m], padded
    __shared__ __align__(16) float Bs[16][128];   // [k][n]
    const int tid = threadIdx.x;
    const int tx = tid & 15, ty = tid >> 4;
    const int bm = blockIdx.x * 128;
    const int bn = blockIdx.y * 128;
    float acc[8][8];
#pragma unroll
    for (int i = 0; i < 8; i++)
#pragma unroll
        for (int j = 0; j < 8; j++) acc[i][j] = 0.f;

    for (int kk = 0; kk < K; kk += 16) {
#pragma unroll
        for (int i = 0; i < 2; i++) {           // A tile: 128x16 = 512 float4
            int f4  = tid + i * 256;
            int row = f4 >> 2;
            int c4  = (f4 & 3) << 2;
            float4 v = make_float4(0.f, 0.f, 0.f, 0.f);
            int gr = bm + row;
            if (gr < M) v = *(const float4*)(A + (size_t)gr * K + kk + c4);
            if (LAYER2) {                        // relu fused into A-load
                v.x = fmaxf(v.x, 0.f); v.y = fmaxf(v.y, 0.f);
                v.z = fmaxf(v.z, 0.f); v.w = fmaxf(v.w, 0.f);
            }
            As[c4 + 0][row] = v.x; As[c4 + 1][row] = v.y;
            As[c4 + 2][row] = v.z; As[c4 + 3][row] = v.w;
        }
#pragma unroll
        for (int i = 0; i < 2; i++) {           // B tile: 16x128 = 512 float4
            int f4  = tid + i * 256;
            int row = f4 >> 5;
            int col = (f4 & 31) << 2;
            *(float4*)&Bs[row][col] = *(const float4*)(B + (size_t)(kk + row) * NCOL + bn + col);
        }
        __syncthreads();
#pragma unroll
        for (int k = 0; k < 16; k++) {
            float a[8], b[8];
#pragma unroll
            for (int i = 0; i < 8; i++) a[i] = As[k][ty * 8 + i];
#pragma unroll
            for (int j = 0; j < 8; j++) b[j] = Bs[k][tx * 8 + j];
#pragma unroll
            for (int i = 0; i < 8; i++)
#pragma unroll
                for (int j = 0; j < 8; j++)
                    acc[i][j] = fmaf(a[i], b[j], acc[i][j]);
        }
        __syncthreads();
    }
#pragma unroll
    for (int i = 0; i < 8; i++) {
        int gr = bm + ty * 8 + i;
        if (gr < M) {
#pragma unroll
            for (int j = 0; j < 8; j += 4) {
                float4 v = make_float4(acc[i][j], acc[i][j + 1], acc[i][j + 2], acc[i][j + 3]);
                *(float4*)(C + (size_t)gr * NCOL + bn + tx * 8 + j) = v;
            }
        }
    }
}

// per-node aggregation: acc[n] = G[n, root] + bias + sum_e w_e * G[src_e, et_e*256:]
__global__ void aggregate(const float* __restrict__ bias) {
    int n = blockIdx.x;
    int tid = threadIdx.x;                       // 128 threads, 2 floats each
    const float* rootrow = d_G + (size_t)n * NCOL + N_REL * HID;
    float2 sum;
    sum.x = rootrow[2 * tid]     + bias[2 * tid];
    sum.y = rootrow[2 * tid + 1] + bias[2 * tid + 1];
    int beg = d_offs[n], end = d_offs[n + 1];
    for (int e = beg; e < end; e++) {
        int pk   = d_elist[e];
        float w  = d_ew[e];
        int srcn = pk & 0xFFFFF;
        int t    = pk >> 20;
        const float2* grow = (const float2*)(d_G + (size_t)srcn * NCOL + t * HID);
        float2 v = grow[tid];
        sum.x = fmaf(v.x, w, sum.x);
        sum.y = fmaf(v.y, w, sum.y);
    }
    ((float2*)(d_acc + (size_t)n * HID))[tid] = sum;
}

// pooled[g] += relu(acc[n]) / gcnt[g]
__global__ void pool_nodes() {
    int n = blockIdx.x;
    int d = threadIdx.x;
    int g = min(max(RP_batch[n], 0), N_GRAPHS - 1);
    float v = d_acc[(size_t)n * HID + d];
    v = fmaxf(v, 0.f) * d_invg[g];
    atomicAdd(&d_pooled[g * HID + d], v);
}

// out[g] = pooled[g] @ lin_w + lin_b   (one warp per (g, class))
__global__ void final_lin(const float* __restrict__ lin_w, const float* __restrict__ lin_b,
                          float* __restrict__ out) {
    int g = blockIdx.x;
    int w = threadIdx.x >> 5;
    int lane = threadIdx.x & 31;
    if (w >= N_CLASS) return;
    float s = 0.f;
    for (int d = lane; d < HID; d += 32)
        s = fmaf(d_pooled[g * HID + d], lin_w[d * N_CLASS + w], s);
#pragma unroll
    for (int off = 16; off; off >>= 1) s += __shfl_down_sync(0xffffffffu, s, off);
    if (lane == 0) out[g * N_CLASS + w] = s + lin_b[w];
}

// ---------------- launch ----------------
extern "C" void kernel_launch(void* const* d_in, const int* in_sizes, int n_in,
                              void* d_out, int out_size) {
    // classify inputs by element count (unique sizes resolve directly)
    int i50[4]  = {-1, -1, -1, -1}; int n50 = 0;
    int i1024[2] = {-1, -1};        int n1024 = 0;
    int i256[2]  = {-1, -1};        int n256 = 0;
    int iEI = -1, iET = -1, iPE = -1, iW1 = -1, iR1 = -1, iW2 = -1, iR2 = -1, iLW = -1, iLB = -1;
    for (int i = 0; i < n_in; i++) {
        switch (in_sizes[i]) {
            case N_NODES:           if (n50  < 4) i50[n50]     = i; n50++;  break;
            case 1024:              if (n1024 < 2) i1024[n1024] = i; n1024++; break;
            case 256:               if (n256 < 2) i256[n256]   = i; n256++; break;
            case 2 * N_EDGES:       iEI = i; break;
            case N_EDGES:           iET = i; break;
            case 128 * EMB:         iPE = i; break;
            case N_REL * IN_DIM * HID: iW1 = i; break;
            case IN_DIM * HID:      iR1 = i; break;
            case N_REL * HID * HID: iW2 = i; break;
            case HID * HID:         iR2 = i; break;
            case HID * N_CLASS:     iLW = i; break;
            case N_CLASS:           iLB = i; break;
        }
    }
    bool map_ok = (n50 == 4) && (n1024 == 2) && (n256 == 2) &&
                  iEI >= 0 && iET >= 0 && iPE >= 0 && iW1 >= 0 && iR1 >= 0 &&
                  iW2 >= 0 && iR2 >= 0 && iLW >= 0 && iLB >= 0;
    if (!map_ok) {
        SizesParam sp; sp.n = n_in;
        for (int i = 0; i < 24; i++) sp.v[i] = (i < n_in) ? in_sizes[i] : -1;
        chk_mapping_fail<<<1, 1>>>(sp, 1);
        return;
    }

    const int* a0 = (const int*)d_in[i50[0]];
    const int* a1 = (const int*)d_in[i50[1]];
    const int* a2 = (const int*)d_in[i50[2]];
    const int* a3 = (const int*)d_in[i50[3]];
    const float* t0 = (const float*)d_in[i1024[0]];
    const float* t1 = (const float*)d_in[i1024[1]];
    const int*   ei    = (const int*)d_in[iEI];
    const int*   et    = (const int*)d_in[iET];
    const float* pe    = (const float*)d_in[iPE];
    const float* W1    = (const float*)d_in[iW1];
    const float* root1 = (const float*)d_in[iR1];
    const float* b1    = (const float*)d_in[i256[0]];   // b1/b2 identical zero vectors
    const float* W2    = (const float*)d_in[iW2];
    const float* root2 = (const float*)d_in[iR2];
    const float* b2    = (const float*)d_in[i256[1]];
    const float* lin_w = (const float*)d_in[iLW];
    const float* lin_b = (const float*)d_in[iLB];
    float* out = (float*)d_out;

    const int* src = ei;
    const int* dst = ei + N_EDGES;

    zero_misc<<<256, 256>>>();
    classify_ints<<<dim3(64, 4), 256>>>(a0, a1, a2, a3);
    assign_roles<<<1, 1>>>(a0, a1, a2, a3, t0, t1);
    chk_roles<<<1, 1>>>();

    repack_w<<<(IN_DIM * NCOL + 255) / 256, 256>>>(W1, root1, W2, root2);
    chk_w<<<1, 256>>>();
    gather_h0<<<(N_NODES * 96 + 255) / 256, 256>>>(pe);
    chk_h0<<<1, 256>>>();
    count_edges<<<(N_EDGES + 255) / 256, 256>>>(dst, et);
    inv_counts<<<256, 256>>>();
    scan_offsets<<<1, 1024>>>();
    scatter_edges<<<(N_EDGES + 255) / 256, 256>>>(src, dst, et);
    chk_offs<<<1, 32>>>();

    dim3 g1((N_NODES + 127) / 128, NCOL / 128);
    // layer 1
    sgemm_k<IN_DIM, false><<<g1, 256>>>(N_NODES);
    chk_G<<<1, 256>>>();
    aggregate<<<N_NODES, 128>>>(b1);
    chk_acc<<<1, 256>>>();
    // layer 2 (relu fused into A-load inside sgemm)
    sgemm_k<HID, true><<<g1, 256>>>(N_NODES);
    aggregate<<<N_NODES, 128>>>(b2);
    // pooling + classifier (relu fused into pool read)
    pool_nodes<<<N_NODES, HID>>>();
    final_lin<<<N_GRAPHS, 320>>>(lin_w, lin_b, out);
}

// round 9
// speedup vs baseline: 1.8680x; 1.8680x over previous
#include <cuda_runtime.h>
#include <cuda_bf16.h>

// ---------------- problem constants ----------------
#define N_NODES  50000
#define N_EDGES  800000
#define N_REL    3
#define N_GRAPHS 500
#define EMB      128
#define IN_DIM   384      // 3*EMB
#define HID      256
#define NCOL     1024     // 3*HID + HID (relation blocks + root block)
#define N_CLASS  10

// ---------------- scratch (device globals; referenced ONLY from device code!) ----
// Passing a __device__ array from host code passes the host shadow symbol; on
// GB300 (ATS) kernels then silently touch HOST memory. Never do that.
__device__ __align__(16) float d_G[(size_t)N_NODES * NCOL];           // 204.8 MB
__device__ __align__(16) float d_acc[(size_t)N_NODES * HID];          // 51.2 MB
__device__ __align__(16) float d_Wcat1[IN_DIM * NCOL];                // 384x1024
__device__ __align__(16) float d_Wcat2[HID * NCOL];                   // 256x1024
__device__ __align__(16) float d_T[144 * NCOL];                       // layer-1 tables
__device__ int   d_cnt3[N_NODES * N_REL];
__device__ float d_invcnt[N_NODES * N_REL];
__device__ int   d_offs[N_NODES + 1];
__device__ int   d_fill[N_NODES];
__device__ int   d_elist[N_EDGES];                      // src | (etype<<20), sorted by dst
__device__ float d_ew[N_EDGES];                         // 1/cnt weight per sorted edge
__device__ int   d_gcnt[N_GRAPHS];
__device__ float d_invg[N_GRAPHS];
__device__ float d_pooled[N_GRAPHS * HID];

// resolved input pointers (device-side role assignment)
__device__ const int*   RP_s;
__device__ const int*   RP_c;
__device__ const int*   RP_p;
__device__ const int*   RP_batch;
__device__ const float* RP_semb;
__device__ const float* RP_cemb;
__device__ int d_maxv[4];

// ---------------- input resolver ----------------
__global__ void classify_ints(const int* a0, const int* a1, const int* a2, const int* a3) {
    const int* arr[4] = {a0, a1, a2, a3};
    const int* a = arr[blockIdx.y];
    int i = blockIdx.x * blockDim.x + threadIdx.x;
    int stride = gridDim.x * blockDim.x;
    int m = 0;
    for (int k = i; k < N_NODES; k += stride) m = max(m, a[k]);
#pragma unroll
    for (int off = 16; off; off >>= 1) m = max(m, __shfl_xor_sync(0xffffffffu, m, off));
    if ((threadIdx.x & 31) == 0) atomicMax(&d_maxv[blockIdx.y], m);
}

__global__ void assign_roles(const int* a0, const int* a1, const int* a2, const int* a3,
                             const float* t0, const float* t1) {
    const int* arr[4] = {a0, a1, a2, a3};
    int small[2]; int ns = 0; int ip = -1, ib = -1;
    for (int k = 0; k < 4; k++) {
        int m = d_maxv[k];
        if (m <= 7)        { if (ns < 2) small[ns] = k; ns++; }
        else if (m <= 127) ip = k;
        else               ib = k;
    }
    if (ns == 2 && ip >= 0 && ib >= 0) {
        RP_s = arr[small[0]]; RP_c = arr[small[1]];
        RP_p = arr[ip];       RP_batch = arr[ib];
    } else {  // fallback: signature order
        RP_s = a0; RP_c = a1; RP_p = a2; RP_batch = a3;
    }
    RP_semb = t0; RP_cemb = t1;
}

// ---------------- utility kernels ----------------
__global__ void zero_misc() {
    int i = blockIdx.x * blockDim.x + threadIdx.x;
    int stride = gridDim.x * blockDim.x;
    for (int k = i; k < N_NODES * N_REL; k += stride) d_cnt3[k] = 0;
    for (int k = i; k < N_NODES;         k += stride) d_fill[k] = 0;
    for (int k = i; k < N_GRAPHS;        k += stride) d_gcnt[k] = 0;
    for (int k = i; k < N_GRAPHS * HID;  k += stride) d_pooled[k] = 0.f;
    if (i < 4) d_maxv[i] = 0;
}

// Build Wcat = [W_r0 | W_r1 | W_r2 | root] as (K x 1024) row-major, both layers
__global__ void repack_w(const float* __restrict__ W1, const float* __restrict__ root1,
                         const float* __restrict__ W2, const float* __restrict__ root2) {
    int i = blockIdx.x * blockDim.x + threadIdx.x;
    if (i < IN_DIM * NCOL) {
        int k = i >> 10, col = i & 1023;
        float v;
        if (col < N_REL * HID) {
            int r = col >> 8, j = col & 255;
            v = W1[((size_t)r * IN_DIM + k) * HID + j];
        } else {
            v = root1[k * HID + (col - N_REL * HID)];
        }
        d_Wcat1[i] = v;
    }
    if (i < HID * NCOL) {
        int k = i >> 10, col = i & 1023;
        float v;
        if (col < N_REL * HID) {
            int r = col >> 8, j = col & 255;
            v = W2[((size_t)r * HID + k) * HID + j];
        } else {
            v = root2[k * HID + (col - N_REL * HID)];
        }
        d_Wcat2[i] = v;
    }
}

// ---------------- layer-1 factorization ----------------
// T[0:8]    = shape_emb @ Wcat1[  0:128, :]
// T[8:16]   = color_emb @ Wcat1[128:256, :]
// T[16:144] = pos_emb   @ Wcat1[256:384, :]
// Then G1[n] = T[s[n]] + T[8+c[n]] + T[16+p[n]]  ==  h0[n] @ Wcat1  exactly.
__global__ __launch_bounds__(256) void build_tables(const float* __restrict__ pe) {
    int trow = blockIdx.x;                 // 0..143
    __shared__ float Arow[128];
    const float* a; int seg;
    if (trow < 8)       { seg = 0; a = RP_semb + (size_t)trow * EMB; }
    else if (trow < 16) { seg = 1; a = RP_cemb + (size_t)(trow - 8) * EMB; }
    else                { seg = 2; a = pe      + (size_t)(trow - 16) * EMB; }
    if (threadIdx.x < 128) Arow[threadIdx.x] = a[threadIdx.x];
    __syncthreads();
    const float* B = d_Wcat1 + (size_t)seg * 128 * NCOL;
    float acc[4] = {0.f, 0.f, 0.f, 0.f};
    for (int k = 0; k < 128; k++) {
        float av = Arow[k];
        const float* brow = B + (size_t)k * NCOL;
#pragma unroll
        for (int j = 0; j < 4; j++)
            acc[j] = fmaf(av, brow[threadIdx.x + 256 * j], acc[j]);
    }
#pragma unroll
    for (int j = 0; j < 4; j++)
        d_T[(size_t)trow * NCOL + threadIdx.x + 256 * j] = acc[j];
}

// G1[n] = table gather-add (entirely replaces the 39-GFLOP layer-1 SGEMM)
__global__ __launch_bounds__(256) void build_G1() {
    int n = blockIdx.x;
    int t = threadIdx.x;                   // 256 float4 lanes = 1024 floats
    int si = min(max(RP_s[n], 0), 7);
    int ci = min(max(RP_c[n], 0), 7);
    int pi = min(max(RP_p[n], 0), 127);
    const float4* Ts = (const float4*)(d_T + (size_t)si * NCOL);
    const float4* Tc = (const float4*)(d_T + (size_t)(8 + ci) * NCOL);
    const float4* Tp = (const float4*)(d_T + (size_t)(16 + pi) * NCOL);
    float4 x = Ts[t], y = Tc[t], z = Tp[t];
    float4 v = make_float4(x.x + y.x + z.x, x.y + y.y + z.y,
                           x.z + y.z + z.z, x.w + y.w + z.w);
    ((float4*)(d_G + (size_t)n * NCOL))[t] = v;
}

__global__ void count_batch() {
    int i = blockIdx.x * blockDim.x + threadIdx.x;
    if (i < N_NODES) atomicAdd(&d_gcnt[min(max(RP_batch[i], 0), N_GRAPHS - 1)], 1);
}

__global__ void count_edges(const int* __restrict__ dst, const int* __restrict__ et) {
    int i = blockIdx.x * blockDim.x + threadIdx.x;
    if (i < N_EDGES) {
        int d = min(max(dst[i], 0), N_NODES - 1);
        int t = min(max(et[i], 0), N_REL - 1);
        atomicAdd(&d_cnt3[d * N_REL + t], 1);
    }
}

__global__ void inv_counts() {
    int i = blockIdx.x * blockDim.x + threadIdx.x;
    int stride = gridDim.x * blockDim.x;
    for (int k = i; k < N_NODES * N_REL; k += stride)
        d_invcnt[k] = 1.0f / fmaxf((float)d_cnt3[k], 1.0f);
    for (int k = i; k < N_GRAPHS; k += stride)
        d_invg[k] = 1.0f / fmaxf((float)d_gcnt[k], 1.0f);
}

// exclusive scan of per-dst edge counts (single block, sequential tiles)
__global__ void scan_offsets() {
    __shared__ int tile[1024];
    __shared__ int carry_s;
    if (threadIdx.x == 0) carry_s = 0;
    __syncthreads();
    for (int base = 0; base < N_NODES; base += 1024) {
        int n = base + (int)threadIdx.x;
        int v = 0;
        if (n < N_NODES)
            v = d_cnt3[3 * n] + d_cnt3[3 * n + 1] + d_cnt3[3 * n + 2];
        tile[threadIdx.x] = v;
        __syncthreads();
        for (int off = 1; off < 1024; off <<= 1) {
            int t = (threadIdx.x >= (unsigned)off) ? tile[threadIdx.x - off] : 0;
            __syncthreads();
            tile[threadIdx.x] += t;
            __syncthreads();
        }
        if (n < N_NODES) d_offs[n] = carry_s + tile[threadIdx.x] - v;   // exclusive
        __syncthreads();
        if (threadIdx.x == 0) carry_s += tile[1023];
        __syncthreads();
    }
    if (threadIdx.x == 0) d_offs[N_NODES] = carry_s;
}

// counting-sort edges into per-dst contiguous lists, with per-edge 1/cnt weight
__global__ void scatter_edges(const int* __restrict__ src, const int* __restrict__ dst,
                              const int* __restrict__ et) {
    int i = blockIdx.x * blockDim.x + threadIdx.x;
    if (i >= N_EDGES) return;
    int d = min(max(dst[i], 0), N_NODES - 1);
    int t = min(max(et[i], 0), N_REL - 1);
    int sv = min(max(src[i], 0), N_NODES - 1);
    int pos = d_offs[d] + atomicAdd(&d_fill[d], 1);
    if (pos >= 0 && pos < N_EDGES) {
        d_elist[pos] = sv | (t << 20);
        d_ew[pos]    = d_invcnt[d * N_REL + t];
    }
}

// ---------------- layer-2 SGEMM: d_G = relu(d_acc) @ d_Wcat2  (M x 256 x 1024) ----
__global__ __launch_bounds__(256)
void sgemm2(int M) {
    const float* __restrict__ A = d_acc;
    const float* __restrict__ B = d_Wcat2;
    float* __restrict__ C = d_G;

    __shared__ __align__(16) float As[16][132];   // [k][m], padded
    __shared__ __align__(16) float Bs[16][128];   // [k][n]
    const int tid = threadIdx.x;
    const int tx = tid & 15, ty = tid >> 4;
    const int bm = blockIdx.x * 128;
    const int bn = blockIdx.y * 128;
    float acc[8][8];
#pragma unroll
    for (int i = 0; i < 8; i++)
#pragma unroll
        for (int j = 0; j < 8; j++) acc[i][j] = 0.f;

    for (int kk = 0; kk < HID; kk += 16) {
#pragma unroll
        for (int i = 0; i < 2; i++) {           // A tile: 128x16 = 512 float4
            int f4  = tid + i * 256;
            int row = f4 >> 2;
            int c4  = (f4 & 3) << 2;
            float4 v = make_float4(0.f, 0.f, 0.f, 0.f);
            int gr = bm + row;
            if (gr < M) v = *(const float4*)(A + (size_t)gr * HID + kk + c4);
            // relu fused into A-load
            v.x = fmaxf(v.x, 0.f); v.y = fmaxf(v.y, 0.f);
            v.z = fmaxf(v.z, 0.f); v.w = fmaxf(v.w, 0.f);
            As[c4 + 0][row] = v.x; As[c4 + 1][row] = v.y;
            As[c4 + 2][row] = v.z; As[c4 + 3][row] = v.w;
        }
#pragma unroll
        for (int i = 0; i < 2; i++) {           // B tile: 16x128 = 512 float4
            int f4  = tid + i * 256;
            int row = f4 >> 5;
            int col = (f4 & 31) << 2;
            *(float4*)&Bs[row][col] = *(const float4*)(B + (size_t)(kk + row) * NCOL + bn + col);
        }
        __syncthreads();
#pragma unroll
        for (int k = 0; k < 16; k++) {
            float a[8], b[8];
#pragma unroll
            for (int i = 0; i < 8; i++) a[i] = As[k][ty * 8 + i];
#pragma unroll
            for (int j = 0; j < 8; j++) b[j] = Bs[k][tx * 8 + j];
#pragma unroll
            for (int i = 0; i < 8; i++)
#pragma unroll
                for (int j = 0; j < 8; j++)
                    acc[i][j] = fmaf(a[i], b[j], acc[i][j]);
        }
        __syncthreads();
    }
#pragma unroll
    for (int i = 0; i < 8; i++) {
        int gr = bm + ty * 8 + i;
        if (gr < M) {
#pragma unroll
            for (int j = 0; j < 8; j += 4) {
                float4 v = make_float4(acc[i][j], acc[i][j + 1], acc[i][j + 2], acc[i][j + 3]);
                *(float4*)(C + (size_t)gr * NCOL + bn + tx * 8 + j) = v;
            }
        }
    }
}

// per-node aggregation: acc[n] = G[n, root] + bias + sum_e w_e * G[src_e, et_e*256:]
__global__ void aggregate(const float* __restrict__ bias) {
    int n = blockIdx.x;
    int tid = threadIdx.x;                       // 128 threads, 2 floats each
    const float* rootrow = d_G + (size_t)n * NCOL + N_REL * HID;
    float2 sum;
    sum.x = rootrow[2 * tid]     + bias[2 * tid];
    sum.y = rootrow[2 * tid + 1] + bias[2 * tid + 1];
    int beg = d_offs[n], end = d_offs[n + 1];
    for (int e = beg; e < end; e++) {
        int pk   = d_elist[e];
        float w  = d_ew[e];
        int srcn = pk & 0xFFFFF;
        int t    = pk >> 20;
        const float2* grow = (const float2*)(d_G + (size_t)srcn * NCOL + t * HID);
        float2 v = grow[tid];
        sum.x = fmaf(v.x, w, sum.x);
        sum.y = fmaf(v.y, w, sum.y);
    }
    ((float2*)(d_acc + (size_t)n * HID))[tid] = sum;
}

// pooled[g] += relu(acc[n]) / gcnt[g]
__global__ void pool_nodes() {
    int n = blockIdx.x;
    int d = threadIdx.x;
    int g = min(max(RP_batch[n], 0), N_GRAPHS - 1);
    float v = d_acc[(size_t)n * HID + d];
    v = fmaxf(v, 0.f) * d_invg[g];
    atomicAdd(&d_pooled[g * HID + d], v);
}

// out[g] = pooled[g] @ lin_w + lin_b   (one warp per (g, class))
__global__ void final_lin(const float* __restrict__ lin_w, const float* __restrict__ lin_b,
                          float* __restrict__ out) {
    int g = blockIdx.x;
    int w = threadIdx.x >> 5;
    int lane = threadIdx.x & 31;
    if (w >= N_CLASS) return;
    float s = 0.f;
    for (int d = lane; d < HID; d += 32)
        s = fmaf(d_pooled[g * HID + d], lin_w[d * N_CLASS + w], s);
#pragma unroll
    for (int off = 16; off; off >>= 1) s += __shfl_down_sync(0xffffffffu, s, off);
    if (lane == 0) out[g * N_CLASS + w] = s + lin_b[w];
}

// ---------------- launch ----------------
extern "C" void kernel_launch(void* const* d_in, const int* in_sizes, int n_in,
                              void* d_out, int out_size) {
    // classify inputs by element count (unique sizes resolve directly)
    int i50[4]  = {-1, -1, -1, -1}; int n50 = 0;
    int i1024[2] = {-1, -1};        int n1024 = 0;
    int i256[2]  = {-1, -1};        int n256 = 0;
    int iEI = -1, iET = -1, iPE = -1, iW1 = -1, iR1 = -1, iW2 = -1, iR2 = -1, iLW = -1, iLB = -1;
    for (int i = 0; i < n_in; i++) {
        switch (in_sizes[i]) {
            case N_NODES:           if (n50  < 4) i50[n50]     = i; n50++;  break;
            case 1024:              if (n1024 < 2) i1024[n1024] = i; n1024++; break;
            case 256:               if (n256 < 2) i256[n256]   = i; n256++; break;
            case 2 * N_EDGES:       iEI = i; break;
            case N_EDGES:           iET = i; break;
            case 128 * EMB:         iPE = i; break;
            case N_REL * IN_DIM * HID: iW1 = i; break;
            case IN_DIM * HID:      iR1 = i; break;
            case N_REL * HID * HID: iW2 = i; break;
            case HID * HID:         iR2 = i; break;
            case HID * N_CLASS:     iLW = i; break;
            case N_CLASS:           iLB = i; break;
        }
    }
    bool map_ok = (n50 == 4) && (n1024 == 2) && (n256 == 2) &&
                  iEI >= 0 && iET >= 0 && iPE >= 0 && iW1 >= 0 && iR1 >= 0 &&
                  iW2 >= 0 && iR2 >= 0 && iLW >= 0 && iLB >= 0;
    if (!map_ok) return;   // will fail verification loudly

    const int* a0 = (const int*)d_in[i50[0]];
    const int* a1 = (const int*)d_in[i50[1]];
    const int* a2 = (const int*)d_in[i50[2]];
    const int* a3 = (const int*)d_in[i50[3]];
    const float* t0 = (const float*)d_in[i1024[0]];
    const float* t1 = (const float*)d_in[i1024[1]];
    const int*   ei    = (const int*)d_in[iEI];
    const int*   et    = (const int*)d_in[iET];
    const float* pe    = (const float*)d_in[iPE];
    const float* W1    = (const float*)d_in[iW1];
    const float* root1 = (const float*)d_in[iR1];
    const float* b1    = (const float*)d_in[i256[0]];   // b1/b2 identical zero vectors
    const float* W2    = (const float*)d_in[iW2];
    const float* root2 = (const float*)d_in[iR2];
    const float* b2    = (const float*)d_in[i256[1]];
    const float* lin_w = (const float*)d_in[iLW];
    const float* lin_b = (const float*)d_in[iLB];
    float* out = (float*)d_out;

    const int* src = ei;
    const int* dst = ei + N_EDGES;

    zero_misc<<<256, 256>>>();
    classify_ints<<<dim3(64, 4), 256>>>(a0, a1, a2, a3);
    assign_roles<<<1, 1>>>(a0, a1, a2, a3, t0, t1);

    repack_w<<<(IN_DIM * NCOL + 255) / 256, 256>>>(W1, root1, W2, root2);
    count_batch<<<(N_NODES + 255) / 256, 256>>>();
    count_edges<<<(N_EDGES + 255) / 256, 256>>>(dst, et);
    inv_counts<<<256, 256>>>();
    scan_offsets<<<1, 1024>>>();
    scatter_edges<<<(N_EDGES + 255) / 256, 256>>>(src, dst, et);

    // layer 1: factorized through 144-row tables (exactly h0 @ Wcat1)
    build_tables<<<144, 256>>>(pe);
    build_G1<<<N_NODES, 256>>>();
    aggregate<<<N_NODES, 128>>>(b1);

    // layer 2: dense SGEMM (relu fused into A-load)
    dim3 g2((N_NODES + 127) / 128, NCOL / 128);
    sgemm2<<<g2, 256>>>(N_NODES);
    aggregate<<<N_NODES, 128>>>(b2);

    // pooling + classifier (relu fused into pool read)
    pool_nodes<<<N_NODES, HID>>>();
    final_lin<<<N_GRAPHS, 320>>>(lin_w, lin_b, out);
}

// round 15
// speedup vs baseline: 2.4594x; 1.3166x over previous
#include <cuda_runtime.h>
#include <cuda_bf16.h>
#include <cstdint>

// ---------------- problem constants ----------------
#define N_NODES  50000
#define N_EDGES  800000
#define N_REL    3
#define N_GRAPHS 500
#define EMB      128
#define IN_DIM   384      // 3*EMB
#define HID      256
#define NCOL     1024     // 3*HID + HID (relation blocks + root block)
#define N_CLASS  10

// ---------------- scratch (device globals; referenced ONLY from device code!) ----
// Passing a __device__ array from host code passes the host shadow symbol; on
// GB300 (ATS) kernels then silently touch HOST memory. Never do that.
__device__ __align__(16) float d_G[(size_t)N_NODES * NCOL];           // 204.8 MB
__device__ __align__(16) float d_acc[(size_t)N_NODES * HID];          // 51.2 MB
__device__ __align__(16) float d_Wcat1[IN_DIM * NCOL];                // 384x1024
__device__ __align__(16) float d_Wcat2[HID * NCOL];                   // 256x1024
__device__ __align__(16) float d_T[144 * NCOL];                       // layer-1 tables
// B pack: [blk(8)][split(2)][n(128)][k(256)] bf16  (hi split=0, lo split=1)
__device__ __align__(16) __nv_bfloat16 d_Bt[8 * 2 * 128 * 256];
__device__ int   d_cnt3[N_NODES * N_REL];
__device__ float d_invcnt[N_NODES * N_REL];
__device__ int   d_offs[N_NODES + 1];
__device__ int   d_fill[N_NODES];
__device__ int   d_elist[N_EDGES];                      // src | (etype<<20), sorted by dst
__device__ float d_ew[N_EDGES];                         // 1/cnt weight per sorted edge
__device__ int   d_gcnt[N_GRAPHS];
__device__ float d_invg[N_GRAPHS];
__device__ float d_pooled[N_GRAPHS * HID];

// resolved input pointers (device-side role assignment)
__device__ const int*   RP_s;
__device__ const int*   RP_c;
__device__ const int*   RP_p;
__device__ const int*   RP_batch;
__device__ const float* RP_semb;
__device__ const float* RP_cemb;
__device__ int d_maxv[4];

// ---------------- generic-PTX tensor helpers (NO tcgen05 — compute_103 target!) ---
__device__ __forceinline__ uint32_t smem_u32(const void* p) {
    uint32_t a;
    asm("{ .reg .u64 t; cvta.to.shared.u64 t, %1; cvt.u32.u64 %0, t; }" : "=r"(a) : "l"(p));
    return a;
}
__device__ __forceinline__ void ldsm_x4(uint32_t* r, uint32_t addr) {
    asm volatile("ldmatrix.sync.aligned.m8n8.x4.shared.b16 {%0,%1,%2,%3}, [%4];"
                 : "=r"(r[0]), "=r"(r[1]), "=r"(r[2]), "=r"(r[3]) : "r"(addr));
}
__device__ __forceinline__ void mma16816(float* d, const uint32_t* a, uint32_t b0, uint32_t b1) {
    asm volatile(
        "mma.sync.aligned.m16n8k16.row.col.f32.bf16.bf16.f32 "
        "{%0,%1,%2,%3}, {%4,%5,%6,%7}, {%8,%9}, {%0,%1,%2,%3};"
        : "+f"(d[0]), "+f"(d[1]), "+f"(d[2]), "+f"(d[3])
        : "r"(a[0]), "r"(a[1]), "r"(a[2]), "r"(a[3]), "r"(b0), "r"(b1));
}
__device__ __forceinline__ uint32_t pack2(float x, float y) {
    __nv_bfloat162 h = __floats2bfloat162_rn(x, y);
    return *(uint32_t*)&h;
}

// SMEM geometry for gemm2_hmma (halfs)
#define AS_STRIDE 136                 // 272B: 16B-aligned, 2-way ldmatrix phases
#define AS_SPLIT  (128 * AS_STRIDE)   // one A split image (chunk 128 x 64)
#define BS_STRIDE 264                 // 528B: 16B-aligned, 2-way ldmatrix phases
#define BS_SPLIT  (128 * BS_STRIDE)   // one B split image (128 n x 256 k)
#define GH_SMEM_HALFS (2 * AS_SPLIT + 2 * BS_SPLIT)
#define GH_SMEM_BYTES (GH_SMEM_HALFS * 2)     // 204800 B

// ---------------- input resolver ----------------
__global__ void classify_ints(const int* a0, const int* a1, const int* a2, const int* a3) {
    const int* arr[4] = {a0, a1, a2, a3};
    const int* a = arr[blockIdx.y];
    int i = blockIdx.x * blockDim.x + threadIdx.x;
    int stride = gridDim.x * blockDim.x;
    int m = 0;
    for (int k = i; k < N_NODES; k += stride) m = max(m, a[k]);
#pragma unroll
    for (int off = 16; off; off >>= 1) m = max(m, __shfl_xor_sync(0xffffffffu, m, off));
    if ((threadIdx.x & 31) == 0) atomicMax(&d_maxv[blockIdx.y], m);
}

__global__ void assign_roles(const int* a0, const int* a1, const int* a2, const int* a3,
                             const float* t0, const float* t1) {
    const int* arr[4] = {a0, a1, a2, a3};
    int small[2]; int ns = 0; int ip = -1, ib = -1;
    for (int k = 0; k < 4; k++) {
        int m = d_maxv[k];
        if (m <= 7)        { if (ns < 2) small[ns] = k; ns++; }
        else if (m <= 127) ip = k;
        else               ib = k;
    }
    if (ns == 2 && ip >= 0 && ib >= 0) {
        RP_s = arr[small[0]]; RP_c = arr[small[1]];
        RP_p = arr[ip];       RP_batch = arr[ib];
    } else {
        RP_s = a0; RP_c = a1; RP_p = a2; RP_batch = a3;
    }
    RP_semb = t0; RP_cemb = t1;
}

// ---------------- utility kernels ----------------
__global__ void zero_misc() {
    int i = blockIdx.x * blockDim.x + threadIdx.x;
    int stride = gridDim.x * blockDim.x;
    for (int k = i; k < N_NODES * N_REL; k += stride) d_cnt3[k] = 0;
    for (int k = i; k < N_NODES;         k += stride) d_fill[k] = 0;
    for (int k = i; k < N_GRAPHS;        k += stride) d_gcnt[k] = 0;
    for (int k = i; k < N_GRAPHS * HID;  k += stride) d_pooled[k] = 0.f;
    if (i < 4) d_maxv[i] = 0;
}

// Build Wcat = [W_r0 | W_r1 | W_r2 | root] as (K x 1024) row-major, both layers
__global__ void repack_w(const float* __restrict__ W1, const float* __restrict__ root1,
                         const float* __restrict__ W2, const float* __restrict__ root2) {
    int i = blockIdx.x * blockDim.x + threadIdx.x;
    if (i < IN_DIM * NCOL) {
        int k = i >> 10, col = i & 1023;
        float v;
        if (col < N_REL * HID) {
            int r = col >> 8, j = col & 255;
            v = W1[((size_t)r * IN_DIM + k) * HID + j];
        } else {
            v = root1[k * HID + (col - N_REL * HID)];
        }
        d_Wcat1[i] = v;
    }
    if (i < HID * NCOL) {
        int k = i >> 10, col = i & 1023;
        float v;
        if (col < N_REL * HID) {
            int r = col >> 8, j = col & 255;
            v = W2[((size_t)r * HID + k) * HID + j];
        } else {
            v = root2[k * HID + (col - N_REL * HID)];
        }
        d_Wcat2[i] = v;
    }
}

// Pre-pack Wcat2 into [blk][split][n][k] bf16 hi/lo (B for gemm2_hmma).
// B[n][k] = Wcat2[k][blk*128 + n].
__global__ void prepack_B() {
    int i = blockIdx.x * blockDim.x + threadIdx.x;   // 8*128*32 = 32768 work items
    if (i >= 8 * 128 * 32) return;
    int blk = i >> 12;
    int rem = i & 4095;
    int n  = rem >> 5;
    int kq = rem & 31;
    int k0 = kq * 8;
    int col = blk * 128 + n;
    uint32_t hiw[4], low[4];
#pragma unroll
    for (int q = 0; q < 4; q++) {
        float v0 = d_Wcat2[(size_t)(k0 + 2 * q)     * NCOL + col];
        float v1 = d_Wcat2[(size_t)(k0 + 2 * q + 1) * NCOL + col];
        __nv_bfloat16 h0 = __float2bfloat16_rn(v0);
        __nv_bfloat16 h1 = __float2bfloat16_rn(v1);
        float r0 = v0 - __bfloat162float(h0);
        float r1 = v1 - __bfloat162float(h1);
        __nv_bfloat16 l0 = __float2bfloat16_rn(r0);
        __nv_bfloat16 l1 = __float2bfloat16_rn(r1);
        hiw[q] = ((uint32_t)*(uint16_t*)&h1 << 16) | *(uint16_t*)&h0;
        low[q] = ((uint32_t)*(uint16_t*)&l1 << 16) | *(uint16_t*)&l0;
    }
    size_t base_hi = (((size_t)blk * 2 + 0) * 128 + n) * 256 + k0;
    size_t base_lo = (((size_t)blk * 2 + 1) * 128 + n) * 256 + k0;
    *(uint4*)(d_Bt + base_hi) = make_uint4(hiw[0], hiw[1], hiw[2], hiw[3]);
    *(uint4*)(d_Bt + base_lo) = make_uint4(low[0], low[1], low[2], low[3]);
}

// ---------------- layer-1 factorization ----------------
__global__ __launch_bounds__(256) void build_tables(const float* __restrict__ pe) {
    int trow = blockIdx.x;                 // 0..143
    __shared__ float Arow[128];
    const float* a; int seg;
    if (trow < 8)       { seg = 0; a = RP_semb + (size_t)trow * EMB; }
    else if (trow < 16) { seg = 1; a = RP_cemb + (size_t)(trow - 8) * EMB; }
    else                { seg = 2; a = pe      + (size_t)(trow - 16) * EMB; }
    if (threadIdx.x < 128) Arow[threadIdx.x] = a[threadIdx.x];
    __syncthreads();
    const float* B = d_Wcat1 + (size_t)seg * 128 * NCOL;
    float acc[4] = {0.f, 0.f, 0.f, 0.f};
    for (int k = 0; k < 128; k++) {
        float av = Arow[k];
        const float* brow = B + (size_t)k * NCOL;
#pragma unroll
        for (int j = 0; j < 4; j++)
            acc[j] = fmaf(av, brow[threadIdx.x + 256 * j], acc[j]);
    }
#pragma unroll
    for (int j = 0; j < 4; j++)
        d_T[(size_t)trow * NCOL + threadIdx.x + 256 * j] = acc[j];
}

__global__ __launch_bounds__(256) void build_G1() {
    int n = blockIdx.x;
    int t = threadIdx.x;
    int si = min(max(RP_s[n], 0), 7);
    int ci = min(max(RP_c[n], 0), 7);
    int pi = min(max(RP_p[n], 0), 127);
    const float4* Ts = (const float4*)(d_T + (size_t)si * NCOL);
    const float4* Tc = (const float4*)(d_T + (size_t)(8 + ci) * NCOL);
    const float4* Tp = (const float4*)(d_T + (size_t)(16 + pi) * NCOL);
    float4 x = Ts[t], y = Tc[t], z = Tp[t];
    float4 v = make_float4(x.x + y.x + z.x, x.y + y.y + z.y,
                           x.z + y.z + z.z, x.w + y.w + z.w);
    ((float4*)(d_G + (size_t)n * NCOL))[t] = v;
}

__global__ void count_batch() {
    int i = blockIdx.x * blockDim.x + threadIdx.x;
    if (i < N_NODES) atomicAdd(&d_gcnt[min(max(RP_batch[i], 0), N_GRAPHS - 1)], 1);
}

__global__ void count_edges(const int* __restrict__ dst, const int* __restrict__ et) {
    int i = blockIdx.x * blockDim.x + threadIdx.x;
    if (i < N_EDGES) {
        int d = min(max(dst[i], 0), N_NODES - 1);
        int t = min(max(et[i], 0), N_REL - 1);
        atomicAdd(&d_cnt3[d * N_REL + t], 1);
    }
}

__global__ void inv_counts() {
    int i = blockIdx.x * blockDim.x + threadIdx.x;
    int stride = gridDim.x * blockDim.x;
    for (int k = i; k < N_NODES * N_REL; k += stride)
        d_invcnt[k] = 1.0f / fmaxf((float)d_cnt3[k], 1.0f);
    for (int k = i; k < N_GRAPHS; k += stride)
        d_invg[k] = 1.0f / fmaxf((float)d_gcnt[k], 1.0f);
}

__global__ void scan_offsets() {
    __shared__ int tile[1024];
    __shared__ int carry_s;
    if (threadIdx.x == 0) carry_s = 0;
    __syncthreads();
    for (int base = 0; base < N_NODES; base += 1024) {
        int n = base + (int)threadIdx.x;
        int v = 0;
        if (n < N_NODES)
            v = d_cnt3[3 * n] + d_cnt3[3 * n + 1] + d_cnt3[3 * n + 2];
        tile[threadIdx.x] = v;
        __syncthreads();
        for (int off = 1; off < 1024; off <<= 1) {
            int t = (threadIdx.x >= (unsigned)off) ? tile[threadIdx.x - off] : 0;
            __syncthreads();
            tile[threadIdx.x] += t;
            __syncthreads();
        }
        if (n < N_NODES) d_offs[n] = carry_s + tile[threadIdx.x] - v;
        __syncthreads();
        if (threadIdx.x == 0) carry_s += tile[1023];
        __syncthreads();
    }
    if (threadIdx.x == 0) d_offs[N_NODES] = carry_s;
}

__global__ void scatter_edges(const int* __restrict__ src, const int* __restrict__ dst,
                              const int* __restrict__ et) {
    int i = blockIdx.x * blockDim.x + threadIdx.x;
    if (i >= N_EDGES) return;
    int d = min(max(dst[i], 0), N_NODES - 1);
    int t = min(max(et[i], 0), N_REL - 1);
    int sv = min(max(src[i], 0), N_NODES - 1);
    int pos = d_offs[d] + atomicAdd(&d_fill[d], 1);
    if (pos >= 0 && pos < N_EDGES) {
        d_elist[pos] = sv | (t << 20);
        d_ew[pos]    = d_invcnt[d * N_REL + t];
    }
}

// ---------------- layer-2 tensor GEMM: d_G = relu(d_acc) @ Wcat2 -----------------
// mma.sync bf16 (generic PTX — works on compute_103), 3-term hi/lo split.
// CTA: 128x128 tile, 256 threads = 8 warps (4 along M x 2 along N; warp = 32x64).
__global__ __launch_bounds__(256, 1)
void gemm2_hmma(int M) {
    extern __shared__ __align__(16) __nv_bfloat16 sh[];
    __nv_bfloat16* Ahi = sh;
    __nv_bfloat16* Alo = sh + AS_SPLIT;
    __nv_bfloat16* Bhi = sh + 2 * AS_SPLIT;
    __nv_bfloat16* Blo = Bhi + BS_SPLIT;

    const int tid  = threadIdx.x;
    const int lane = tid & 31;
    const int wid  = tid >> 5;
    const int wm   = wid & 3;            // warp row (0..3) -> rows wm*32
    const int wn   = wid >> 2;           // warp col (0..1) -> cols wn*64
    const int bm   = blockIdx.x * 128;
    const int blk  = blockIdx.y;         // 128-col block of NCOL

    // --- load B (both splits) into padded SMEM images ---
    {
        const uint4* src = (const uint4*)(d_Bt + (size_t)blk * 2 * 128 * 256);
        for (int i = tid; i < 8192; i += 256) {      // 2 splits * 128 n * 32 kq
            int split = i >> 12;
            int r  = (i & 4095) >> 5;
            int kq = i & 31;
            uint4 v = src[i];
            __nv_bfloat16* dst = split ? Blo : Bhi;
            *(uint4*)(dst + r * BS_STRIDE + kq * 8) = v;
        }
    }

    float acc[16][4];
#pragma unroll
    for (int t = 0; t < 16; t++)
#pragma unroll
        for (int q = 0; q < 4; q++) acc[t][q] = 0.f;

    const uint32_t sAhi = smem_u32(Ahi);
    const uint32_t sAlo = smem_u32(Alo);
    const uint32_t sBhi = smem_u32(Bhi);
    const uint32_t sBlo = smem_u32(Blo);

    for (int kc = 0; kc < 4; kc++) {      // K chunks of 64
        __syncthreads();                  // previous chunk fully consumed
        // --- fill A chunk: 128 rows x 64 cols, relu + hi/lo split ---
#pragma unroll
        for (int it = 0; it < 8; it++) {
            int idx = tid + it * 256;     // 0..2047, 4 floats each
            int r  = idx >> 4;
            int c0 = (idx & 15) * 4;
            float4 x;
            int gr = bm + r;
            if (gr < M) x = *(const float4*)(d_acc + (size_t)gr * HID + kc * 64 + c0);
            else        x = make_float4(0.f, 0.f, 0.f, 0.f);
            x.x = fmaxf(x.x, 0.f); x.y = fmaxf(x.y, 0.f);
            x.z = fmaxf(x.z, 0.f); x.w = fmaxf(x.w, 0.f);
            __nv_bfloat16 h0 = __float2bfloat16_rn(x.x);
            __nv_bfloat16 h1 = __float2bfloat16_rn(x.y);
            __nv_bfloat16 h2 = __float2bfloat16_rn(x.z);
            __nv_bfloat16 h3 = __float2bfloat16_rn(x.w);
            uint32_t hw0 = ((uint32_t)*(uint16_t*)&h1 << 16) | *(uint16_t*)&h0;
            uint32_t hw1 = ((uint32_t)*(uint16_t*)&h3 << 16) | *(uint16_t*)&h2;
            uint32_t lw0 = pack2(x.x - __bfloat162float(h0), x.y - __bfloat162float(h1));
            uint32_t lw1 = pack2(x.z - __bfloat162float(h2), x.w - __bfloat162float(h3));
            *(uint2*)(Ahi + r * AS_STRIDE + c0) = make_uint2(hw0, hw1);
            *(uint2*)(Alo + r * AS_STRIDE + c0) = make_uint2(lw0, lw1);
        }
        __syncthreads();

        // --- 4 ksteps of 16 within this chunk ---
#pragma unroll
        for (int ks = 0; ks < 4; ks++) {
            uint32_t ah[2][4], al[2][4];
#pragma unroll
            for (int mt = 0; mt < 2; mt++) {
                int r0 = wm * 32 + mt * 16;
                uint32_t off = (uint32_t)(r0 + (lane & 15)) * (AS_STRIDE * 2)
                             + (uint32_t)ks * 32 + (lane >> 4) * 16;
                ldsm_x4(ah[mt], sAhi + off);
                ldsm_x4(al[mt], sAlo + off);
            }
            uint32_t bh[4][4], bl[4][4];
#pragma unroll
            for (int np = 0; np < 4; np++) {
                int n0 = wn * 64 + np * 16;
                uint32_t off = (uint32_t)(n0 + (lane & 15)) * (BS_STRIDE * 2)
                             + (uint32_t)(kc * 64 + ks * 16) * 2 + (lane >> 4) * 16;
                ldsm_x4(bh[np], sBhi + off);
                ldsm_x4(bl[np], sBlo + off);
            }
#pragma unroll
            for (int mt = 0; mt < 2; mt++) {
#pragma unroll
                for (int np = 0; np < 4; np++) {
                    int t0 = mt * 8 + np * 2;
                    // n-tile 0 of pair uses regs {0,2}; tile 1 uses {1,3}
                    mma16816(acc[t0],     ah[mt], bh[np][0], bh[np][2]);
                    mma16816(acc[t0],     ah[mt], bl[np][0], bl[np][2]);
                    mma16816(acc[t0],     al[mt], bh[np][0], bh[np][2]);
                    mma16816(acc[t0 + 1], ah[mt], bh[np][1], bh[np][3]);
                    mma16816(acc[t0 + 1], ah[mt], bl[np][1], bl[np][3]);
                    mma16816(acc[t0 + 1], al[mt], bh[np][1], bh[np][3]);
                }
            }
        }
    }

    // --- epilogue: fragment -> d_G ---
#pragma unroll
    for (int mt = 0; mt < 2; mt++) {
#pragma unroll
        for (int np = 0; np < 4; np++) {
#pragma unroll
            for (int sub = 0; sub < 2; sub++) {
                int t = mt * 8 + np * 2 + sub;
                int col = blk * 128 + wn * 64 + np * 16 + sub * 8 + (lane & 3) * 2;
                int r0  = bm + wm * 32 + mt * 16 + (lane >> 2);
                if (r0 < M)
                    *(float2*)(d_G + (size_t)r0 * NCOL + col) = make_float2(acc[t][0], acc[t][1]);
                if (r0 + 8 < M)
                    *(float2*)(d_G + (size_t)(r0 + 8) * NCOL + col) = make_float2(acc[t][2], acc[t][3]);
            }
        }
    }
}

// per-node aggregation: acc[n] = G[n, root] + bias + sum_e w_e * G[src_e, et_e*256:]
__global__ void aggregate(const float* __restrict__ bias) {
    int n = blockIdx.x;
    int tid = threadIdx.x;                       // 128 threads, 2 floats each
    const float* rootrow = d_G + (size_t)n * NCOL + N_REL * HID;
    float2 sum;
    sum.x = rootrow[2 * tid]     + bias[2 * tid];
    sum.y = rootrow[2 * tid + 1] + bias[2 * tid + 1];
    int beg = d_offs[n], end = d_offs[n + 1];
    for (int e = beg; e < end; e++) {
        int pk   = d_elist[e];
        float w  = d_ew[e];
        int srcn = pk & 0xFFFFF;
        int t    = pk >> 20;
        const float2* grow = (const float2*)(d_G + (size_t)srcn * NCOL + t * HID);
        float2 v = grow[tid];
        sum.x = fmaf(v.x, w, sum.x);
        sum.y = fmaf(v.y, w, sum.y);
    }
    ((float2*)(d_acc + (size_t)n * HID))[tid] = sum;
}

// pooled[g] += relu(acc[n]) / gcnt[g]
__global__ void pool_nodes() {
    int n = blockIdx.x;
    int d = threadIdx.x;
    int g = min(max(RP_batch[n], 0), N_GRAPHS - 1);
    float v = d_acc[(size_t)n * HID + d];
    v = fmaxf(v, 0.f) * d_invg[g];
    atomicAdd(&d_pooled[g * HID + d], v);
}

// out[g] = pooled[g] @ lin_w + lin_b
__global__ void final_lin(const float* __restrict__ lin_w, const float* __restrict__ lin_b,
                          float* __restrict__ out) {
    int g = blockIdx.x;
    int w = threadIdx.x >> 5;
    int lane = threadIdx.x & 31;
    if (w >= N_CLASS) return;
    float s = 0.f;
    for (int d = lane; d < HID; d += 32)
        s = fmaf(d_pooled[g * HID + d], lin_w[d * N_CLASS + w], s);
#pragma unroll
    for (int off = 16; off; off >>= 1) s += __shfl_down_sync(0xffffffffu, s, off);
    if (lane == 0) out[g * N_CLASS + w] = s + lin_b[w];
}

// ---------------- launch ----------------
extern "C" void kernel_launch(void* const* d_in, const int* in_sizes, int n_in,
                              void* d_out, int out_size) {
    int i50[4]  = {-1, -1, -1, -1}; int n50 = 0;
    int i1024[2] = {-1, -1};        int n1024 = 0;
    int i256[2]  = {-1, -1};        int n256 = 0;
    int iEI = -1, iET = -1, iPE = -1, iW1 = -1, iR1 = -1, iW2 = -1, iR2 = -1, iLW = -1, iLB = -1;
    for (int i = 0; i < n_in; i++) {
        switch (in_sizes[i]) {
            case N_NODES:           if (n50  < 4) i50[n50]     = i; n50++;  break;
            case 1024:              if (n1024 < 2) i1024[n1024] = i; n1024++; break;
            case 256:               if (n256 < 2) i256[n256]   = i; n256++; break;
            case 2 * N_EDGES:       iEI = i; break;
            case N_EDGES:           iET = i; break;
            case 128 * EMB:         iPE = i; break;
            case N_REL * IN_DIM * HID: iW1 = i; break;
            case IN_DIM * HID:      iR1 = i; break;
            case N_REL * HID * HID: iW2 = i; break;
            case HID * HID:         iR2 = i; break;
            case HID * N_CLASS:     iLW = i; break;
            case N_CLASS:           iLB = i; break;
        }
    }
    bool map_ok = (n50 == 4) && (n1024 == 2) && (n256 == 2) &&
                  iEI >= 0 && iET >= 0 && iPE >= 0 && iW1 >= 0 && iR1 >= 0 &&
                  iW2 >= 0 && iR2 >= 0 && iLW >= 0 && iLB >= 0;
    if (!map_ok) return;

    const int* a0 = (const int*)d_in[i50[0]];
    const int* a1 = (const int*)d_in[i50[1]];
    const int* a2 = (const int*)d_in[i50[2]];
    const int* a3 = (const int*)d_in[i50[3]];
    const float* t0 = (const float*)d_in[i1024[0]];
    const float* t1 = (const float*)d_in[i1024[1]];
    const int*   ei    = (const int*)d_in[iEI];
    const int*   et    = (const int*)d_in[iET];
    const float* pe    = (const float*)d_in[iPE];
    const float* W1    = (const float*)d_in[iW1];
    const float* root1 = (const float*)d_in[iR1];
    const float* b1    = (const float*)d_in[i256[0]];
    const float* W2    = (const float*)d_in[iW2];
    const float* root2 = (const float*)d_in[iR2];
    const float* b2    = (const float*)d_in[i256[1]];
    const float* lin_w = (const float*)d_in[iLW];
    const float* lin_b = (const float*)d_in[iLB];
    float* out = (float*)d_out;

    const int* src = ei;
    const int* dst = ei + N_EDGES;

    static bool attr_done = false;
    if (!attr_done) {
        cudaFuncSetAttribute(gemm2_hmma, cudaFuncAttributeMaxDynamicSharedMemorySize,
                             GH_SMEM_BYTES);
        attr_done = true;
    }

    zero_misc<<<256, 256>>>();
    classify_ints<<<dim3(64, 4), 256>>>(a0, a1, a2, a3);
    assign_roles<<<1, 1>>>(a0, a1, a2, a3, t0, t1);

    repack_w<<<(IN_DIM * NCOL + 255) / 256, 256>>>(W1, root1, W2, root2);
    prepack_B<<<128, 256>>>();
    count_batch<<<(N_NODES + 255) / 256, 256>>>();
    count_edges<<<(N_EDGES + 255) / 256, 256>>>(dst, et);
    inv_counts<<<256, 256>>>();
    scan_offsets<<<1, 1024>>>();
    scatter_edges<<<(N_EDGES + 255) / 256, 256>>>(src, dst, et);

    // layer 1: factorized through 144-row tables (exactly h0 @ Wcat1)
    build_tables<<<144, 256>>>(pe);
    build_G1<<<N_NODES, 256>>>();
    aggregate<<<N_NODES, 128>>>(b1);

    // layer 2: bf16-split HMMA GEMM (relu fused into A conversion)
    dim3 g2((N_NODES + 127) / 128, NCOL / 128);
    gemm2_hmma<<<g2, 256, GH_SMEM_BYTES>>>(N_NODES);
    aggregate<<<N_NODES, 128>>>(b2);

    // pooling + classifier
    pool_nodes<<<N_NODES, HID>>>();
    final_lin<<<N_GRAPHS, 320>>>(lin_w, lin_b, out);
}

// round 16
// speedup vs baseline: 2.7721x; 1.1271x over previous
#include <cuda_runtime.h>
#include <cuda_bf16.h>
#include <cstdint>

// ---------------- problem constants ----------------
#define N_NODES  50000
#define N_EDGES  800000
#define N_REL    3
#define N_GRAPHS 500
#define EMB      128
#define IN_DIM   384      // 3*EMB
#define HID      256
#define NCOL     1024     // 3*HID + HID (relation blocks + root block)
#define RELCOL   768      // 3*HID
#define N_CLASS  10

// ---------------- scratch (device globals; referenced ONLY from device code!) ----
// Passing a __device__ array from host code passes the host shadow symbol; on
// GB300 (ATS) kernels then silently touch HOST memory. Never do that.
__device__ __align__(16) __nv_bfloat16 d_Grel[(size_t)N_NODES * RELCOL]; // 76.8 MB
__device__ __align__(16) float d_Groot[(size_t)N_NODES * HID];           // 51.2 MB
__device__ __align__(16) float d_acc[(size_t)N_NODES * HID];             // 51.2 MB
__device__ __align__(16) float d_Wcat1[IN_DIM * NCOL];                   // 384x1024
__device__ __align__(16) float d_Wcat2[HID * NCOL];                      // 256x1024
__device__ __align__(16) float d_T[144 * NCOL];                          // layer-1 tables
// B pack: [blk(8)][split(2)][n(128)][k(256)] bf16  (hi split=0, lo split=1)
__device__ __align__(16) __nv_bfloat16 d_Bt[8 * 2 * 128 * 256];
__device__ int   d_cnt3[N_NODES * N_REL];
__device__ float d_invcnt[N_NODES * N_REL];
__device__ int   d_offs[N_NODES + 1];
__device__ int   d_fill[N_NODES];
__device__ int   d_elist[N_EDGES];                      // src | (etype<<20), sorted by dst
__device__ float d_ew[N_EDGES];                         // 1/cnt weight per sorted edge
__device__ int   d_gcnt[N_GRAPHS];
__device__ float d_invg[N_GRAPHS];
__device__ float d_pooled[N_GRAPHS * HID];

// resolved input pointers (device-side role assignment)
__device__ const int*   RP_s;
__device__ const int*   RP_c;
__device__ const int*   RP_p;
__device__ const int*   RP_batch;
__device__ const float* RP_semb;
__device__ const float* RP_cemb;
__device__ int d_maxv[4];

// ---------------- generic-PTX tensor helpers (NO tcgen05 — compute_103 target!) ---
__device__ __forceinline__ uint32_t smem_u32(const void* p) {
    uint32_t a;
    asm("{ .reg .u64 t; cvta.to.shared.u64 t, %1; cvt.u32.u64 %0, t; }" : "=r"(a) : "l"(p));
    return a;
}
__device__ __forceinline__ void ldsm_x4(uint32_t* r, uint32_t addr) {
    asm volatile("ldmatrix.sync.aligned.m8n8.x4.shared.b16 {%0,%1,%2,%3}, [%4];"
                 : "=r"(r[0]), "=r"(r[1]), "=r"(r[2]), "=r"(r[3]) : "r"(addr));
}
__device__ __forceinline__ void mma16816(float* d, const uint32_t* a, uint32_t b0, uint32_t b1) {
    asm volatile(
        "mma.sync.aligned.m16n8k16.row.col.f32.bf16.bf16.f32 "
        "{%0,%1,%2,%3}, {%4,%5,%6,%7}, {%8,%9}, {%0,%1,%2,%3};"
        : "+f"(d[0]), "+f"(d[1]), "+f"(d[2]), "+f"(d[3])
        : "r"(a[0]), "r"(a[1]), "r"(a[2]), "r"(a[3]), "r"(b0), "r"(b1));
}
__device__ __forceinline__ uint32_t pack2(float x, float y) {
    __nv_bfloat162 h = __floats2bfloat162_rn(x, y);
    return *(uint32_t*)&h;
}

// SMEM geometry for gemm2_hmma (halfs)
#define AS_STRIDE 136                 // 272B: 16B-aligned, 2-way ldmatrix phases
#define AS_SPLIT  (128 * AS_STRIDE)   // one A split image (chunk 128 x 64)
#define BS_STRIDE 264                 // 528B: 16B-aligned, 2-way ldmatrix phases
#define BS_SPLIT  (128 * BS_STRIDE)   // one B split image (128 n x 256 k)
#define GH_SMEM_HALFS (2 * AS_SPLIT + 2 * BS_SPLIT)
#define GH_SMEM_BYTES (GH_SMEM_HALFS * 2)     // 204800 B

// ---------------- input resolver ----------------
__global__ void classify_ints(const int* a0, const int* a1, const int* a2, const int* a3) {
    const int* arr[4] = {a0, a1, a2, a3};
    const int* a = arr[blockIdx.y];
    int i = blockIdx.x * blockDim.x + threadIdx.x;
    int stride = gridDim.x * blockDim.x;
    int m = 0;
    for (int k = i; k < N_NODES; k += stride) m = max(m, a[k]);
#pragma unroll
    for (int off = 16; off; off >>= 1) m = max(m, __shfl_xor_sync(0xffffffffu, m, off));
    if ((threadIdx.x & 31) == 0) atomicMax(&d_maxv[blockIdx.y], m);
}

__global__ void assign_roles(const int* a0, const int* a1, const int* a2, const int* a3,
                             const float* t0, const float* t1) {
    const int* arr[4] = {a0, a1, a2, a3};
    int small[2]; int ns = 0; int ip = -1, ib = -1;
    for (int k = 0; k < 4; k++) {
        int m = d_maxv[k];
        if (m <= 7)        { if (ns < 2) small[ns] = k; ns++; }
        else if (m <= 127) ip = k;
        else               ib = k;
    }
    if (ns == 2 && ip >= 0 && ib >= 0) {
        RP_s = arr[small[0]]; RP_c = arr[small[1]];
        RP_p = arr[ip];       RP_batch = arr[ib];
    } else {
        RP_s = a0; RP_c = a1; RP_p = a2; RP_batch = a3;
    }
    RP_semb = t0; RP_cemb = t1;
}

// ---------------- utility kernels ----------------
__global__ void zero_misc() {
    int i = blockIdx.x * blockDim.x + threadIdx.x;
    int stride = gridDim.x * blockDim.x;
    for (int k = i; k < N_NODES * N_REL; k += stride) d_cnt3[k] = 0;
    for (int k = i; k < N_NODES;         k += stride) d_fill[k] = 0;
    for (int k = i; k < N_GRAPHS;        k += stride) d_gcnt[k] = 0;
    for (int k = i; k < N_GRAPHS * HID;  k += stride) d_pooled[k] = 0.f;
    if (i < 4) d_maxv[i] = 0;
}

// Build Wcat = [W_r0 | W_r1 | W_r2 | root] as (K x 1024) row-major, both layers
__global__ void repack_w(const float* __restrict__ W1, const float* __restrict__ root1,
                         const float* __restrict__ W2, const float* __restrict__ root2) {
    int i = blockIdx.x * blockDim.x + threadIdx.x;
    if (i < IN_DIM * NCOL) {
        int k = i >> 10, col = i & 1023;
        float v;
        if (col < N_REL * HID) {
            int r = col >> 8, j = col & 255;
            v = W1[((size_t)r * IN_DIM + k) * HID + j];
        } else {
            v = root1[k * HID + (col - N_REL * HID)];
        }
        d_Wcat1[i] = v;
    }
    if (i < HID * NCOL) {
        int k = i >> 10, col = i & 1023;
        float v;
        if (col < N_REL * HID) {
            int r = col >> 8, j = col & 255;
            v = W2[((size_t)r * HID + k) * HID + j];
        } else {
            v = root2[k * HID + (col - N_REL * HID)];
        }
        d_Wcat2[i] = v;
    }
}

// Pre-pack Wcat2 into [blk][split][n][k] bf16 hi/lo (B for gemm2_hmma).
// B[n][k] = Wcat2[k][blk*128 + n].
__global__ void prepack_B() {
    int i = blockIdx.x * blockDim.x + threadIdx.x;   // 8*128*32 = 32768 work items
    if (i >= 8 * 128 * 32) return;
    int blk = i >> 12;
    int rem = i & 4095;
    int n  = rem >> 5;
    int kq = rem & 31;
    int k0 = kq * 8;
    int col = blk * 128 + n;
    uint32_t hiw[4], low[4];
#pragma unroll
    for (int q = 0; q < 4; q++) {
        float v0 = d_Wcat2[(size_t)(k0 + 2 * q)     * NCOL + col];
        float v1 = d_Wcat2[(size_t)(k0 + 2 * q + 1) * NCOL + col];
        __nv_bfloat16 h0 = __float2bfloat16_rn(v0);
        __nv_bfloat16 h1 = __float2bfloat16_rn(v1);
        float r0 = v0 - __bfloat162float(h0);
        float r1 = v1 - __bfloat162float(h1);
        __nv_bfloat16 l0 = __float2bfloat16_rn(r0);
        __nv_bfloat16 l1 = __float2bfloat16_rn(r1);
        hiw[q] = ((uint32_t)*(uint16_t*)&h1 << 16) | *(uint16_t*)&h0;
        low[q] = ((uint32_t)*(uint16_t*)&l1 << 16) | *(uint16_t*)&l0;
    }
    size_t base_hi = (((size_t)blk * 2 + 0) * 128 + n) * 256 + k0;
    size_t base_lo = (((size_t)blk * 2 + 1) * 128 + n) * 256 + k0;
    *(uint4*)(d_Bt + base_hi) = make_uint4(hiw[0], hiw[1], hiw[2], hiw[3]);
    *(uint4*)(d_Bt + base_lo) = make_uint4(low[0], low[1], low[2], low[3]);
}

// ---------------- layer-1 factorization ----------------
__global__ __launch_bounds__(256) void build_tables(const float* __restrict__ pe) {
    int trow = blockIdx.x;                 // 0..143
    __shared__ float Arow[128];
    const float* a; int seg;
    if (trow < 8)       { seg = 0; a = RP_semb + (size_t)trow * EMB; }
    else if (trow < 16) { seg = 1; a = RP_cemb + (size_t)(trow - 8) * EMB; }
    else                { seg = 2; a = pe      + (size_t)(trow - 16) * EMB; }
    if (threadIdx.x < 128) Arow[threadIdx.x] = a[threadIdx.x];
    __syncthreads();
    const float* B = d_Wcat1 + (size_t)seg * 128 * NCOL;
    float acc[4] = {0.f, 0.f, 0.f, 0.f};
    for (int k = 0; k < 128; k++) {
        float av = Arow[k];
        const float* brow = B + (size_t)k * NCOL;
#pragma unroll
        for (int j = 0; j < 4; j++)
            acc[j] = fmaf(av, brow[threadIdx.x + 256 * j], acc[j]);
    }
#pragma unroll
    for (int j = 0; j < 4; j++)
        d_T[(size_t)trow * NCOL + threadIdx.x + 256 * j] = acc[j];
}

// G1[n] = table gather-add; relation blocks stored bf16, root block fp32.
__global__ __launch_bounds__(256) void build_G1() {
    int n = blockIdx.x;
    int t = threadIdx.x;                 // element base 4t (0..1020)
    int si = min(max(RP_s[n], 0), 7);
    int ci = min(max(RP_c[n], 0), 7);
    int pi = min(max(RP_p[n], 0), 127);
    const float4* Ts = (const float4*)(d_T + (size_t)si * NCOL);
    const float4* Tc = (const float4*)(d_T + (size_t)(8 + ci) * NCOL);
    const float4* Tp = (const float4*)(d_T + (size_t)(16 + pi) * NCOL);
    float4 x = Ts[t], y = Tc[t], z = Tp[t];
    float4 v = make_float4(x.x + y.x + z.x, x.y + y.y + z.y,
                           x.z + y.z + z.z, x.w + y.w + z.w);
    if (t < 192) {                       // relation block -> bf16
        uint32_t p0 = pack2(v.x, v.y);
        uint32_t p1 = pack2(v.z, v.w);
        *(uint2*)(d_Grel + (size_t)n * RELCOL + 4 * t) = make_uint2(p0, p1);
    } else {                             // root block -> fp32
        *(float4*)(d_Groot + (size_t)n * HID + 4 * t - RELCOL) = v;
    }
}

__global__ void count_batch() {
    int i = blockIdx.x * blockDim.x + threadIdx.x;
    if (i < N_NODES) atomicAdd(&d_gcnt[min(max(RP_batch[i], 0), N_GRAPHS - 1)], 1);
}

__global__ void count_edges(const int* __restrict__ dst, const int* __restrict__ et) {
    int i = blockIdx.x * blockDim.x + threadIdx.x;
    if (i < N_EDGES) {
        int d = min(max(dst[i], 0), N_NODES - 1);
        int t = min(max(et[i], 0), N_REL - 1);
        atomicAdd(&d_cnt3[d * N_REL + t], 1);
    }
}

__global__ void inv_counts() {
    int i = blockIdx.x * blockDim.x + threadIdx.x;
    int stride = gridDim.x * blockDim.x;
    for (int k = i; k < N_NODES * N_REL; k += stride)
        d_invcnt[k] = 1.0f / fmaxf((float)d_cnt3[k], 1.0f);
    for (int k = i; k < N_GRAPHS; k += stride)
        d_invg[k] = 1.0f / fmaxf((float)d_gcnt[k], 1.0f);
}

__global__ void scan_offsets() {
    __shared__ int tile[1024];
    __shared__ int carry_s;
    if (threadIdx.x == 0) carry_s = 0;
    __syncthreads();
    for (int base = 0; base < N_NODES; base += 1024) {
        int n = base + (int)threadIdx.x;
        int v = 0;
        if (n < N_NODES)
            v = d_cnt3[3 * n] + d_cnt3[3 * n + 1] + d_cnt3[3 * n + 2];
        tile[threadIdx.x] = v;
        __syncthreads();
        for (int off = 1; off < 1024; off <<= 1) {
            int t = (threadIdx.x >= (unsigned)off) ? tile[threadIdx.x - off] : 0;
            __syncthreads();
            tile[threadIdx.x] += t;
            __syncthreads();
        }
        if (n < N_NODES) d_offs[n] = carry_s + tile[threadIdx.x] - v;
        __syncthreads();
        if (threadIdx.x == 0) carry_s += tile[1023];
        __syncthreads();
    }
    if (threadIdx.x == 0) d_offs[N_NODES] = carry_s;
}

__global__ void scatter_edges(const int* __restrict__ src, const int* __restrict__ dst,
                              const int* __restrict__ et) {
    int i = blockIdx.x * blockDim.x + threadIdx.x;
    if (i >= N_EDGES) return;
    int d = min(max(dst[i], 0), N_NODES - 1);
    int t = min(max(et[i], 0), N_REL - 1);
    int sv = min(max(src[i], 0), N_NODES - 1);
    int pos = d_offs[d] + atomicAdd(&d_fill[d], 1);
    if (pos >= 0 && pos < N_EDGES) {
        d_elist[pos] = sv | (t << 20);
        d_ew[pos]    = d_invcnt[d * N_REL + t];
    }
}

// ---------------- layer-2 tensor GEMM: G2 = relu(d_acc) @ Wcat2 -----------------
// mma.sync bf16 (generic PTX — works on compute_103), 3-term hi/lo split.
// CTA: 128x128 tile, 256 threads = 8 warps (4 along M x 2 along N; warp = 32x64).
// Epilogue: cols < 768 -> bf16 d_Grel, cols >= 768 -> fp32 d_Groot.
__global__ __launch_bounds__(256, 1)
void gemm2_hmma(int M) {
    extern __shared__ __align__(16) __nv_bfloat16 sh[];
    __nv_bfloat16* Ahi = sh;
    __nv_bfloat16* Alo = sh + AS_SPLIT;
    __nv_bfloat16* Bhi = sh + 2 * AS_SPLIT;
    __nv_bfloat16* Blo = Bhi + BS_SPLIT;

    const int tid  = threadIdx.x;
    const int lane = tid & 31;
    const int wid  = tid >> 5;
    const int wm   = wid & 3;            // warp row (0..3) -> rows wm*32
    const int wn   = wid >> 2;           // warp col (0..1) -> cols wn*64
    const int bm   = blockIdx.x * 128;
    const int blk  = blockIdx.y;         // 128-col block of NCOL

    // --- load B (both splits) into padded SMEM images ---
    {
        const uint4* src = (const uint4*)(d_Bt + (size_t)blk * 2 * 128 * 256);
        for (int i = tid; i < 8192; i += 256) {      // 2 splits * 128 n * 32 kq
            int split = i >> 12;
            int r  = (i & 4095) >> 5;
            int kq = i & 31;
            uint4 v = src[i];
            __nv_bfloat16* dst = split ? Blo : Bhi;
            *(uint4*)(dst + r * BS_STRIDE + kq * 8) = v;
        }
    }

    float acc[16][4];
#pragma unroll
    for (int t = 0; t < 16; t++)
#pragma unroll
        for (int q = 0; q < 4; q++) acc[t][q] = 0.f;

    const uint32_t sAhi = smem_u32(Ahi);
    const uint32_t sAlo = smem_u32(Alo);
    const uint32_t sBhi = smem_u32(Bhi);
    const uint32_t sBlo = smem_u32(Blo);

    for (int kc = 0; kc < 4; kc++) {      // K chunks of 64
        __syncthreads();                  // previous chunk fully consumed
        // --- fill A chunk: 128 rows x 64 cols, relu + hi/lo split ---
#pragma unroll
        for (int it = 0; it < 8; it++) {
            int idx = tid + it * 256;     // 0..2047, 4 floats each
            int r  = idx >> 4;
            int c0 = (idx & 15) * 4;
            float4 x;
            int gr = bm + r;
            if (gr < M) x = *(const float4*)(d_acc + (size_t)gr * HID + kc * 64 + c0);
            else        x = make_float4(0.f, 0.f, 0.f, 0.f);
            x.x = fmaxf(x.x, 0.f); x.y = fmaxf(x.y, 0.f);
            x.z = fmaxf(x.z, 0.f); x.w = fmaxf(x.w, 0.f);
            __nv_bfloat16 h0 = __float2bfloat16_rn(x.x);
            __nv_bfloat16 h1 = __float2bfloat16_rn(x.y);
            __nv_bfloat16 h2 = __float2bfloat16_rn(x.z);
            __nv_bfloat16 h3 = __float2bfloat16_rn(x.w);
            uint32_t hw0 = ((uint32_t)*(uint16_t*)&h1 << 16) | *(uint16_t*)&h0;
            uint32_t hw1 = ((uint32_t)*(uint16_t*)&h3 << 16) | *(uint16_t*)&h2;
            uint32_t lw0 = pack2(x.x - __bfloat162float(h0), x.y - __bfloat162float(h1));
            uint32_t lw1 = pack2(x.z - __bfloat162float(h2), x.w - __bfloat162float(h3));
            *(uint2*)(Ahi + r * AS_STRIDE + c0) = make_uint2(hw0, hw1);
            *(uint2*)(Alo + r * AS_STRIDE + c0) = make_uint2(lw0, lw1);
        }
        __syncthreads();

        // --- 4 ksteps of 16 within this chunk ---
#pragma unroll
        for (int ks = 0; ks < 4; ks++) {
            uint32_t ah[2][4], al[2][4];
#pragma unroll
            for (int mt = 0; mt < 2; mt++) {
                int r0 = wm * 32 + mt * 16;
                uint32_t off = (uint32_t)(r0 + (lane & 15)) * (AS_STRIDE * 2)
                             + (uint32_t)ks * 32 + (lane >> 4) * 16;
                ldsm_x4(ah[mt], sAhi + off);
                ldsm_x4(al[mt], sAlo + off);
            }
            uint32_t bh[4][4], bl[4][4];
#pragma unroll
            for (int np = 0; np < 4; np++) {
                int n0 = wn * 64 + np * 16;
                uint32_t off = (uint32_t)(n0 + (lane & 15)) * (BS_STRIDE * 2)
                             + (uint32_t)(kc * 64 + ks * 16) * 2 + (lane >> 4) * 16;
                ldsm_x4(bh[np], sBhi + off);
                ldsm_x4(bl[np], sBlo + off);
            }
#pragma unroll
            for (int mt = 0; mt < 2; mt++) {
#pragma unroll
                for (int np = 0; np < 4; np++) {
                    int t0 = mt * 8 + np * 2;
                    // n-tile 0 of pair uses regs {0,2}; tile 1 uses {1,3}
                    mma16816(acc[t0],     ah[mt], bh[np][0], bh[np][2]);
                    mma16816(acc[t0],     ah[mt], bl[np][0], bl[np][2]);
                    mma16816(acc[t0],     al[mt], bh[np][0], bh[np][2]);
                    mma16816(acc[t0 + 1], ah[mt], bh[np][1], bh[np][3]);
                    mma16816(acc[t0 + 1], ah[mt], bl[np][1], bl[np][3]);
                    mma16816(acc[t0 + 1], al[mt], bh[np][1], bh[np][3]);
                }
            }
        }
    }

    // --- epilogue: fragment -> d_Grel (bf16) / d_Groot (fp32) ---
#pragma unroll
    for (int mt = 0; mt < 2; mt++) {
#pragma unroll
        for (int np = 0; np < 4; np++) {
#pragma unroll
            for (int sub = 0; sub < 2; sub++) {
                int t = mt * 8 + np * 2 + sub;
                int colg = blk * 128 + wn * 64 + np * 16 + sub * 8 + (lane & 3) * 2;
                int r0   = bm + wm * 32 + mt * 16 + (lane >> 2);
                if (colg < RELCOL) {
                    if (r0 < M)
                        *(uint32_t*)(d_Grel + (size_t)r0 * RELCOL + colg) =
                            pack2(acc[t][0], acc[t][1]);
                    if (r0 + 8 < M)
                        *(uint32_t*)(d_Grel + (size_t)(r0 + 8) * RELCOL + colg) =
                            pack2(acc[t][2], acc[t][3]);
                } else {
                    int cr = colg - RELCOL;
                    if (r0 < M)
                        *(float2*)(d_Groot + (size_t)r0 * HID + cr) =
                            make_float2(acc[t][0], acc[t][1]);
                    if (r0 + 8 < M)
                        *(float2*)(d_Groot + (size_t)(r0 + 8) * HID + cr) =
                            make_float2(acc[t][2], acc[t][3]);
                }
            }
        }
    }
}

// per-node aggregation: acc[n] = Groot[n] + bias + sum_e w_e * Grel[src_e, et_e block]
// Grel rows are bf16; dual accumulators double MLP on the latency-bound gathers.
__global__ void aggregate(const float* __restrict__ bias) {
    int n = blockIdx.x;
    int tid = threadIdx.x;                       // 128 threads, 2 elements each
    float2 rv = ((const float2*)(d_Groot + (size_t)n * HID))[tid];
    float2 sum, sum2;
    sum.x = rv.x + bias[2 * tid];
    sum.y = rv.y + bias[2 * tid + 1];
    sum2.x = 0.f; sum2.y = 0.f;
    int e = d_offs[n], end = d_offs[n + 1];
    for (; e + 1 < end; e += 2) {
        int pk0 = d_elist[e], pk1 = d_elist[e + 1];
        float w0 = d_ew[e],   w1 = d_ew[e + 1];
        const uint32_t* r0 = (const uint32_t*)(d_Grel +
            (size_t)(pk0 & 0xFFFFF) * RELCOL + (pk0 >> 20) * HID);
        const uint32_t* r1 = (const uint32_t*)(d_Grel +
            (size_t)(pk1 & 0xFFFFF) * RELCOL + (pk1 >> 20) * HID);
        uint32_t u0 = r0[tid], u1 = r1[tid];
        float2 f0 = __bfloat1622float2(*(__nv_bfloat162*)&u0);
        float2 f1 = __bfloat1622float2(*(__nv_bfloat162*)&u1);
        sum.x  = fmaf(f0.x, w0, sum.x);
        sum.y  = fmaf(f0.y, w0, sum.y);
        sum2.x = fmaf(f1.x, w1, sum2.x);
        sum2.y = fmaf(f1.y, w1, sum2.y);
    }
    if (e < end) {
        int pk = d_elist[e];
        float w = d_ew[e];
        const uint32_t* r0 = (const uint32_t*)(d_Grel +
            (size_t)(pk & 0xFFFFF) * RELCOL + (pk >> 20) * HID);
        uint32_t u = r0[tid];
        float2 f = __bfloat1622float2(*(__nv_bfloat162*)&u);
        sum.x = fmaf(f.x, w, sum.x);
        sum.y = fmaf(f.y, w, sum.y);
    }
    sum.x += sum2.x; sum.y += sum2.y;
    ((float2*)(d_acc + (size_t)n * HID))[tid] = sum;
}

// pooled[g] += relu(acc[n]) / gcnt[g]
__global__ void pool_nodes() {
    int n = blockIdx.x;
    int d = threadIdx.x;
    int g = min(max(RP_batch[n], 0), N_GRAPHS - 1);
    float v = d_acc[(size_t)n * HID + d];
    v = fmaxf(v, 0.f) * d_invg[g];
    atomicAdd(&d_pooled[g * HID + d], v);
}

// out[g] = pooled[g] @ lin_w + lin_b
__global__ void final_lin(const float* __restrict__ lin_w, const float* __restrict__ lin_b,
                          float* __restrict__ out) {
    int g = blockIdx.x;
    int w = threadIdx.x >> 5;
    int lane = threadIdx.x & 31;
    if (w >= N_CLASS) return;
    float s = 0.f;
    for (int d = lane; d < HID; d += 32)
        s = fmaf(d_pooled[g * HID + d], lin_w[d * N_CLASS + w], s);
#pragma unroll
    for (int off = 16; off; off >>= 1) s += __shfl_down_sync(0xffffffffu, s, off);
    if (lane == 0) out[g * N_CLASS + w] = s + lin_b[w];
}

// ---------------- launch ----------------
extern "C" void kernel_launch(void* const* d_in, const int* in_sizes, int n_in,
                              void* d_out, int out_size) {
    int i50[4]  = {-1, -1, -1, -1}; int n50 = 0;
    int i1024[2] = {-1, -1};        int n1024 = 0;
    int i256[2]  = {-1, -1};        int n256 = 0;
    int iEI = -1, iET = -1, iPE = -1, iW1 = -1, iR1 = -1, iW2 = -1, iR2 = -1, iLW = -1, iLB = -1;
    for (int i = 0; i < n_in; i++) {
        switch (in_sizes[i]) {
            case N_NODES:           if (n50  < 4) i50[n50]     = i; n50++;  break;
            case 1024:              if (n1024 < 2) i1024[n1024] = i; n1024++; break;
            case 256:               if (n256 < 2) i256[n256]   = i; n256++; break;
            case 2 * N_EDGES:       iEI = i; break;
            case N_EDGES:           iET = i; break;
            case 128 * EMB:         iPE = i; break;
            case N_REL * IN_DIM * HID: iW1 = i; break;
            case IN_DIM * HID:      iR1 = i; break;
            case N_REL * HID * HID: iW2 = i; break;
            case HID * HID:         iR2 = i; break;
            case HID * N_CLASS:     iLW = i; break;
            case N_CLASS:           iLB = i; break;
        }
    }
    bool map_ok = (n50 == 4) && (n1024 == 2) && (n256 == 2) &&
                  iEI >= 0 && iET >= 0 && iPE >= 0 && iW1 >= 0 && iR1 >= 0 &&
                  iW2 >= 0 && iR2 >= 0 && iLW >= 0 && iLB >= 0;
    if (!map_ok) return;

    const int* a0 = (const int*)d_in[i50[0]];
    const int* a1 = (const int*)d_in[i50[1]];
    const int* a2 = (const int*)d_in[i50[2]];
    const int* a3 = (const int*)d_in[i50[3]];
    const float* t0 = (const float*)d_in[i1024[0]];
    const float* t1 = (const float*)d_in[i1024[1]];
    const int*   ei    = (const int*)d_in[iEI];
    const int*   et    = (const int*)d_in[iET];
    const float* pe    = (const float*)d_in[iPE];
    const float* W1    = (const float*)d_in[iW1];
    const float* root1 = (const float*)d_in[iR1];
    const float* b1    = (const float*)d_in[i256[0]];
    const float* W2    = (const float*)d_in[iW2];
    const float* root2 = (const float*)d_in[iR2];
    const float* b2    = (const float*)d_in[i256[1]];
    const float* lin_w = (const float*)d_in[iLW];
    const float* lin_b = (const float*)d_in[iLB];
    float* out = (float*)d_out;

    const int* src = ei;
    const int* dst = ei + N_EDGES;

    static bool attr_done = false;
    if (!attr_done) {
        cudaFuncSetAttribute(gemm2_hmma, cudaFuncAttributeMaxDynamicSharedMemorySize,
                             GH_SMEM_BYTES);
        attr_done = true;
    }

    zero_misc<<<256, 256>>>();
    classify_ints<<<dim3(64, 4), 256>>>(a0, a1, a2, a3);
    assign_roles<<<1, 1>>>(a0, a1, a2, a3, t0, t1);

    repack_w<<<(IN_DIM * NCOL + 255) / 256, 256>>>(W1, root1, W2, root2);
    prepack_B<<<128, 256>>>();
    count_batch<<<(N_NODES + 255) / 256, 256>>>();
    count_edges<<<(N_EDGES + 255) / 256, 256>>>(dst, et);
    inv_counts<<<256, 256>>>();
    scan_offsets<<<1, 1024>>>();
    scatter_edges<<<(N_EDGES + 255) / 256, 256>>>(src, dst, et);

    // layer 1: factorized through 144-row tables (exactly h0 @ Wcat1)
    build_tables<<<144, 256>>>(pe);
    build_G1<<<N_NODES, 256>>>();
    aggregate<<<N_NODES, 128>>>(b1);

    // layer 2: bf16-split HMMA GEMM (relu fused into A conversion)
    dim3 g2((N_NODES + 127) / 128, NCOL / 128);
    gemm2_hmma<<<g2, 256, GH_SMEM_BYTES>>>(N_NODES);
    aggregate<<<N_NODES, 128>>>(b2);

    // pooling + classifier
    pool_nodes<<<N_NODES, HID>>>();
    final_lin<<<N_GRAPHS, 320>>>(lin_w, lin_b, out);
}